// round 15
// baseline (speedup 1.0000x reference)
#include <cuda_runtime.h>
#include <cuda_fp16.h>
#include <math.h>
#include <stdint.h>

// ---------------- problem constants ----------------
#define BB    2
#define SS    2048
#define HID   2048
#define NH    16
#define NKV   4
#define DQK   192
#define DV    128
#define LORA  512
#define QKVN  3584                 // NH*DQK + LORA
#define NROWS 4096                 // BB*SS
#define KDIM  768                  // NKV*DQK
#define VDIM  512                  // NKV*DV
#define KVD   1280                 // KDIM + VDIM
#define ODIM  2048                 // NH*DV
#define QDIM  3072                 // NH*DQK

// ---------------- scratch (static device globals) ----------------
__device__ __align__(256) float  g_ropet[SS * 64];
__device__ __align__(256) __half g_hsh  [(size_t)NROWS * HID];
__device__ __align__(256) __half g_wqkvT[(size_t)QKVN * HID];    // [N][K]
__device__ __align__(256) __half g_wkvT [(size_t)KVD * LORA];    // [N][K], k rows then v rows
__device__ __align__(256) __half g_qkvh [(size_t)NROWS * QKVN];  // fp16 GEMM1 out: q | c_kv
__device__ __align__(256) __half g_kvh  [(size_t)NROWS * KVD];   // fp16 GEMM2 out: k | v
__device__ __align__(256) __half g_attnh[(size_t)NROWS * ODIM];
__device__ __align__(256) __half g_woT  [(size_t)HID * ODIM];    // [N=HID][K=ODIM]

// ---------------- helpers ----------------
__device__ __forceinline__ uint32_t smaddr(const void* p) {
    return (uint32_t)__cvta_generic_to_shared(p);
}
__device__ __forceinline__ uint32_t pack2(float x, float y) {
    __half2 h = __floats2half2_rn(x, y);
    return *(uint32_t*)&h;
}
__device__ __forceinline__ void store2(float* p, float a, float b) {
    *(float2*)p = make_float2(a, b);
}
__device__ __forceinline__ void store2(__half* p, float a, float b) {
    *(uint32_t*)p = pack2(a, b);
}
#define CP16(dst, src) \
    asm volatile("cp.async.cg.shared.global [%0], [%1], 16;" :: "r"(dst), "l"(src) : "memory")
#define CP_COMMIT() asm volatile("cp.async.commit_group;" ::: "memory")
#define CP_WAIT(n)  asm volatile("cp.async.wait_group %0;" :: "n"(n) : "memory")

#define LDSM_X4(r0,r1,r2,r3,addr) \
    asm volatile("ldmatrix.sync.aligned.m8n8.x4.shared.b16 {%0,%1,%2,%3}, [%4];" \
                 : "=r"(r0), "=r"(r1), "=r"(r2), "=r"(r3) : "r"(addr))
#define LDSM_X4_T(r0,r1,r2,r3,addr) \
    asm volatile("ldmatrix.sync.aligned.m8n8.x4.trans.shared.b16 {%0,%1,%2,%3}, [%4];" \
                 : "=r"(r0), "=r"(r1), "=r"(r2), "=r"(r3) : "r"(addr))
#define MMA16816(c0,c1,c2,c3,a0,a1,a2,a3,b0,b1) \
    asm volatile("mma.sync.aligned.m16n8k16.row.col.f32.f16.f16.f32 " \
                 "{%0,%1,%2,%3}, {%4,%5,%6,%7}, {%8,%9}, {%0,%1,%2,%3};" \
                 : "+f"(c0), "+f"(c1), "+f"(c2), "+f"(c3) \
                 : "r"(a0), "r"(a1), "r"(a2), "r"(a3), "r"(b0), "r"(b1))

// ---------------- pipelined half GEMM: C[M,N] = A[M,K]h @ Bt[N,K]h ----------------
// BM x 128 x 64 CTA tile, 256 threads, 3-stage cp.async pipeline (R7 barrier order).
// BM=256: 4m x 2n warps, warp tile 64x64.  BM=128: 2m x 4n warps, warp tile 64x32.
// 72-half row pad: 144B row stride -> 16B rotation per row -> conflict-free ldmatrix.
template <int BM> struct GCfg {
    static const int NSTG = 3;
    static const int ASTG = BM * 72;
    static const int BSTG = 128 * 72;
    static const int STG  = ASTG + BSTG;
    static const int SMEM = NSTG * STG * 2;     // BM=256: 165888, BM=128: 110592
};

template <typename OutT, int BM>
__global__ void __launch_bounds__(256, 1) hgemm(
    const __half* __restrict__ A, int lda,
    const __half* __restrict__ Bt, int ldb,
    OutT* __restrict__ C, int ldc, int K)
{
    constexpr int NSTG  = GCfg<BM>::NSTG;
    constexpr int ASTG_ = GCfg<BM>::ASTG;
    constexpr int STG   = GCfg<BM>::STG;
    constexpr int NI    = (BM == 256) ? 8 : 4;    // n-frags per warp
    constexpr int APASS = BM / 32;                // 32 rows per 256-thread pass

    extern __shared__ __half hsm[];
    const int tid = threadIdx.x, lane = tid & 31, warp = tid >> 5;
    const int wm = (BM == 256) ? (warp >> 1) * 64 : (warp >> 2) * 64;
    const int wn = (BM == 256) ? (warp & 1) * 64  : (warp & 3) * 32;
    const int m0 = blockIdx.y * BM, n0 = blockIdx.x * 128;
    const int g = lane >> 2, q2 = (lane & 3) * 2;
    const int lr8 = tid >> 3, lc8 = (tid & 7) * 8;   // 32 rows x 64 halves per pass
    const int nchunk = K >> 6;

    float acc[4][NI][4];
    #pragma unroll
    for (int mi = 0; mi < 4; mi++)
        #pragma unroll
        for (int ni = 0; ni < NI; ni++)
            #pragma unroll
            for (int e = 0; e < 4; e++) acc[mi][ni][e] = 0.f;

    // prefetch stages 0..NSTG-2
    #pragma unroll
    for (int p = 0; p < NSTG - 1; p++) {
        __half* As = hsm + p * STG;
        __half* Bs = As + ASTG_;
        int k0 = p * 64;
        #pragma unroll
        for (int bk = 0; bk < APASS; bk++)
            CP16(smaddr(&As[(lr8 + 32 * bk) * 72 + lc8]),
                 &A[(size_t)(m0 + 32 * bk + lr8) * lda + k0 + lc8]);
        #pragma unroll
        for (int bk = 0; bk < 4; bk++)
            CP16(smaddr(&Bs[(lr8 + 32 * bk) * 72 + lc8]),
                 &Bt[(size_t)(n0 + 32 * bk + lr8) * ldb + k0 + lc8]);
        CP_COMMIT();
    }

    for (int c = 0; c < nchunk; c++) {
        CP_WAIT(NSTG - 2);
        __syncthreads();
        const int s = c % NSTG;
        __half* As = hsm + s * STG;
        __half* Bs = As + ASTG_;

        #pragma unroll
        for (int kk = 0; kk < 4; kk++) {
            const int ks = kk * 16;
            uint32_t a[4][4], bf[NI][2];
            #pragma unroll
            for (int mi = 0; mi < 4; mi++) {
                uint32_t ad = smaddr(&As[(wm + mi * 16 + (lane & 15)) * 72 + ks + (lane >> 4) * 8]);
                LDSM_X4(a[mi][0], a[mi][1], a[mi][2], a[mi][3], ad);
            }
            #pragma unroll
            for (int nj = 0; nj < NI / 2; nj++) {
                uint32_t bd = smaddr(&Bs[(wn + nj * 16 + (lane & 7) + ((lane >> 4) & 1) * 8) * 72
                                         + ks + ((lane >> 3) & 1) * 8]);
                LDSM_X4(bf[2*nj][0], bf[2*nj][1], bf[2*nj+1][0], bf[2*nj+1][1], bd);
            }
            #pragma unroll
            for (int mi = 0; mi < 4; mi++)
                #pragma unroll
                for (int ni = 0; ni < NI; ni++)
                    MMA16816(acc[mi][ni][0], acc[mi][ni][1], acc[mi][ni][2], acc[mi][ni][3],
                             a[mi][0], a[mi][1], a[mi][2], a[mi][3], bf[ni][0], bf[ni][1]);
        }
        __syncthreads();   // all reads of stage (c+NSTG-1)%NSTG done before refill

        if (c + NSTG - 1 < nchunk) {
            const int s2 = (c + NSTG - 1) % NSTG;
            __half* As2 = hsm + s2 * STG;
            __half* Bs2 = As2 + ASTG_;
            int k0 = (c + NSTG - 1) * 64;
            #pragma unroll
            for (int bk = 0; bk < APASS; bk++)
                CP16(smaddr(&As2[(lr8 + 32 * bk) * 72 + lc8]),
                     &A[(size_t)(m0 + 32 * bk + lr8) * lda + k0 + lc8]);
            #pragma unroll
            for (int bk = 0; bk < 4; bk++)
                CP16(smaddr(&Bs2[(lr8 + 32 * bk) * 72 + lc8]),
                     &Bt[(size_t)(n0 + 32 * bk + lr8) * ldb + k0 + lc8]);
        }
        CP_COMMIT();
    }

    #pragma unroll
    for (int mi = 0; mi < 4; mi++)
        #pragma unroll
        for (int ni = 0; ni < NI; ni++) {
            int row = m0 + wm + mi * 16 + g;
            int col = n0 + wn + ni * 8 + q2;
            store2(C + (size_t)row * ldc + col,       acc[mi][ni][0], acc[mi][ni][1]);
            store2(C + (size_t)(row + 8) * ldc + col, acc[mi][ni][2], acc[mi][ni][3]);
        }
}

// ---------------- conversions ----------------
__global__ void f2h_slice(const float* __restrict__ src, int ld, int cols, int rows,
                          __half* __restrict__ dst)
{
    int i = blockIdx.x * blockDim.x + threadIdx.x;
    int total = rows * (cols >> 2);
    if (i >= total) return;
    int row = i / (cols >> 2);
    int c4  = (i - row * (cols >> 2)) << 2;
    float4 v = *(const float4*)&src[(size_t)row * ld + c4];
    __half2 h0 = __floats2half2_rn(v.x, v.y);
    __half2 h1 = __floats2half2_rn(v.z, v.w);
    uint2 o = make_uint2(*(uint32_t*)&h0, *(uint32_t*)&h1);
    *(uint2*)&dst[(size_t)row * cols + c4] = o;
}

// all four weight transposes fused: flat block id -> segment
#define T0 7168   // Wqkv: (QKVN/32)*(HID/32)
#define T1 384    // Wk:   (KDIM/32)*(LORA/32)
#define T2 256    // Wv:   (VDIM/32)*(LORA/32)
#define T3 4096   // Wo:   (HID/32)*(ODIM/32)
__global__ void transp_all(const float* __restrict__ Wqkv, const float* __restrict__ Wk,
                           const float* __restrict__ Wv,   const float* __restrict__ Wo,
                           __half* __restrict__ wqkvT, __half* __restrict__ wkvT,
                           __half* __restrict__ woT)
{
    __shared__ float t[32][33];
    int id = blockIdx.x;
    const float* W; __half* Wt; int K, N, nx;
    if (id < T0)                  { W = Wqkv; Wt = wqkvT; K = HID;  N = QKVN; nx = QKVN/32; }
    else if ((id -= T0) < T1)     { W = Wk;   Wt = wkvT;  K = LORA; N = KDIM; nx = KDIM/32; }
    else if ((id -= T1) < T2)     { W = Wv;   Wt = wkvT + (size_t)KDIM * LORA; K = LORA; N = VDIM; nx = VDIM/32; }
    else { id -= T2;                W = Wo;   Wt = woT;   K = ODIM; N = HID;  nx = HID/32; }
    int n0 = (id % nx) * 32, k0 = (id / nx) * 32;
    int tx = threadIdx.x, ty = threadIdx.y;   // 32 x 8
    #pragma unroll
    for (int i = 0; i < 4; i++)
        t[ty + i * 8][tx] = W[(size_t)(k0 + ty + i * 8) * N + n0 + tx];
    __syncthreads();
    #pragma unroll
    for (int i = 0; i < 4; i++)
        Wt[(size_t)(n0 + ty + i * 8) * K + k0 + tx] = __float2half(t[tx][ty + i * 8]);
}

// ---------------- RoPE ----------------
__global__ void rope_table(float* __restrict__ tab)
{
    int i = blockIdx.x * blockDim.x + threadIdx.x;
    if (i >= SS * 32) return;
    int t = i >> 5, p = i & 31;
    double f = exp(-((double)(2 * p) / 64.0) * log(10000.0));
    double sd, cd;
    sincos((double)t * f, &sd, &cd);
    tab[t * 64 + p]      = (float)cd;
    tab[t * 64 + 32 + p] = (float)sd;
}

__global__ void rope_apply_h(__half* __restrict__ qkvh, __half* __restrict__ kvh,
                             const float* __restrict__ tab)
{
    int i = blockIdx.x * blockDim.x + threadIdx.x;
    const int total = NROWS * 20 * 32;
    if (i >= total) return;
    int p    = i & 31;
    int rest = i >> 5;
    int slot = rest % 20;
    int row  = rest / 20;
    int t    = row & (SS - 1);
    __half* base = (slot < 16)
        ? (qkvh + (size_t)row * QKVN + slot * DQK + 128)
        : (kvh  + (size_t)row * KVD + (slot - 16) * DQK + 128);
    float c = tab[t * 64 + p], s = tab[t * 64 + 32 + p];
    float x1 = __half2float(base[p]), x2 = __half2float(base[p + 32]);
    base[p]      = __float2half(x1 * c - x2 * s);
    base[p + 32] = __float2half(x2 * c + x1 * s);
}

// ---------------- flash attention (mma, causal, GQA, cp.async double-buffer) ----------------
// R7 structure (two barriers per tile) — proven baseline, untouched this round.
#define QW 200
#define VW 136
#define ATTN_SMEM ((128*QW + 2*64*QW + 2*64*VW) * 2)   // 137216 bytes

__global__ void __launch_bounds__(256, 1) attn_kernel(
    const __half* __restrict__ qp, int ldq,
    const __half* __restrict__ kp2, int ldk,
    const __half* __restrict__ vp2, int ldv,
    __half* __restrict__ oh)
{
    extern __shared__ __half sh[];
    __half* Qs  = sh;                     // [128][QW]
    __half* Ksb = sh + 128 * QW;          // 2 x [64][QW]
    __half* Vsb = Ksb + 2 * 64 * QW;      // 2 x [64][VW]

    const int qt   = gridDim.x - 1 - blockIdx.x;
    const int h    = blockIdx.y, b = blockIdx.z, hkv = h >> 2;
    const int tid  = threadIdx.x, lane = tid & 31, warp = tid >> 5;
    const int g    = lane >> 2, q2 = (lane & 3) * 2;
    const float scale = 0.07216878364870323f;

    for (int f = tid; f < 128 * 24; f += 256) {
        int r = f / 24, c = (f % 24) * 8;
        CP16(smaddr(&Qs[r * QW + c]),
             &qp[(size_t)(b * SS + qt * 128 + r) * ldq + h * DQK + c]);
    }
    {
        const __half* kp = &kp2[(size_t)(b * SS) * ldk + hkv * DQK];
        const __half* vp = &vp2[(size_t)(b * SS) * ldv + hkv * DV];
        for (int f = tid; f < 64 * 24; f += 256) {
            int r = f / 24, c = (f % 24) * 8;
            CP16(smaddr(&Ksb[r * QW + c]), kp + (size_t)r * ldk + c);
        }
        for (int f = tid; f < 64 * 16; f += 256) {
            int r = f / 16, c = (f % 16) * 8;
            CP16(smaddr(&Vsb[r * VW + c]), vp + (size_t)r * ldv + c);
        }
    }
    CP_COMMIT();

    float oacc[16][4];
    #pragma unroll
    for (int ni = 0; ni < 16; ni++)
        #pragma unroll
        for (int e = 0; e < 4; e++) oacc[ni][e] = 0.f;
    float m0 = -1e30f, m1 = -1e30f, l0 = 0.f, l1 = 0.f;

    const int row0 = qt * 128 + warp * 16 + g;
    const int ktend = 2 * qt + 1;

    for (int kt = 0; kt <= ktend; kt++) {
        if (kt < ktend) {
            __half* Kn = Ksb + ((kt + 1) & 1) * 64 * QW;
            __half* Vn = Vsb + ((kt + 1) & 1) * 64 * VW;
            const __half* kp = &kp2[(size_t)(b * SS + (kt + 1) * 64) * ldk + hkv * DQK];
            const __half* vp = &vp2[(size_t)(b * SS + (kt + 1) * 64) * ldv + hkv * DV];
            for (int f = tid; f < 64 * 24; f += 256) {
                int r = f / 24, c = (f % 24) * 8;
                CP16(smaddr(&Kn[r * QW + c]), kp + (size_t)r * ldk + c);
            }
            for (int f = tid; f < 64 * 16; f += 256) {
                int r = f / 16, c = (f % 16) * 8;
                CP16(smaddr(&Vn[r * VW + c]), vp + (size_t)r * ldv + c);
            }
        }
        CP_COMMIT();
        CP_WAIT(1);
        __syncthreads();

        __half* Ks = Ksb + (kt & 1) * 64 * QW;
        __half* Vs = Vsb + (kt & 1) * 64 * VW;

        // ---- S = Q @ K^T ----
        float sacc[8][4];
        #pragma unroll
        for (int j = 0; j < 8; j++)
            #pragma unroll
            for (int e = 0; e < 4; e++) sacc[j][e] = 0.f;

        #pragma unroll
        for (int ks = 0; ks < 12; ks++) {
            uint32_t a0, a1, a2, a3;
            uint32_t ad = smaddr(&Qs[(warp * 16 + (lane & 15)) * QW + ks * 16 + (lane >> 4) * 8]);
            LDSM_X4(a0, a1, a2, a3, ad);
            uint32_t bk[8][2];
            #pragma unroll
            for (int nj = 0; nj < 4; nj++) {
                uint32_t bd = smaddr(&Ks[(nj * 16 + (lane & 7) + ((lane >> 4) & 1) * 8) * QW
                                         + ks * 16 + ((lane >> 3) & 1) * 8]);
                LDSM_X4(bk[2*nj][0], bk[2*nj][1], bk[2*nj+1][0], bk[2*nj+1][1], bd);
            }
            #pragma unroll
            for (int nj = 0; nj < 8; nj++)
                MMA16816(sacc[nj][0], sacc[nj][1], sacc[nj][2], sacc[nj][3],
                         a0, a1, a2, a3, bk[nj][0], bk[nj][1]);
        }

        // ---- scale + mask + online softmax ----
        const bool diag = (kt >= 2 * qt);
        float mx0 = -1e30f, mx1 = -1e30f;
        #pragma unroll
        for (int j = 0; j < 8; j++) {
            #pragma unroll
            for (int e = 0; e < 4; e++) {
                float v = sacc[j][e] * scale;
                if (diag) {
                    int col = kt * 64 + j * 8 + q2 + (e & 1);
                    int row = row0 + ((e >= 2) ? 8 : 0);
                    if (col > row) v = -1e30f;
                }
                sacc[j][e] = v;
            }
            mx0 = fmaxf(mx0, fmaxf(sacc[j][0], sacc[j][1]));
            mx1 = fmaxf(mx1, fmaxf(sacc[j][2], sacc[j][3]));
        }
        mx0 = fmaxf(mx0, __shfl_xor_sync(0xffffffffu, mx0, 1));
        mx0 = fmaxf(mx0, __shfl_xor_sync(0xffffffffu, mx0, 2));
        mx1 = fmaxf(mx1, __shfl_xor_sync(0xffffffffu, mx1, 1));
        mx1 = fmaxf(mx1, __shfl_xor_sync(0xffffffffu, mx1, 2));
        float nm0 = fmaxf(m0, mx0), nm1 = fmaxf(m1, mx1);
        float s0 = 0.f, s1 = 0.f;
        #pragma unroll
        for (int j = 0; j < 8; j++) {
            float p0 = __expf(sacc[j][0] - nm0);
            float p1 = __expf(sacc[j][1] - nm0);
            float p2 = __expf(sacc[j][2] - nm1);
            float p3 = __expf(sacc[j][3] - nm1);
            sacc[j][0] = p0; sacc[j][1] = p1; sacc[j][2] = p2; sacc[j][3] = p3;
            s0 += p0 + p1; s1 += p2 + p3;
        }
        s0 += __shfl_xor_sync(0xffffffffu, s0, 1);
        s0 += __shfl_xor_sync(0xffffffffu, s0, 2);
        s1 += __shfl_xor_sync(0xffffffffu, s1, 1);
        s1 += __shfl_xor_sync(0xffffffffu, s1, 2);
        float c0 = __expf(m0 - nm0), c1 = __expf(m1 - nm1);
        l0 = l0 * c0 + s0; l1 = l1 * c1 + s1;
        m0 = nm0; m1 = nm1;
        #pragma unroll
        for (int ni = 0; ni < 16; ni++) {
            oacc[ni][0] *= c0; oacc[ni][1] *= c0;
            oacc[ni][2] *= c1; oacc[ni][3] *= c1;
        }

        uint32_t pa[4][4];
        #pragma unroll
        for (int kk = 0; kk < 4; kk++) {
            pa[kk][0] = pack2(sacc[2*kk][0],   sacc[2*kk][1]);
            pa[kk][1] = pack2(sacc[2*kk][2],   sacc[2*kk][3]);
            pa[kk][2] = pack2(sacc[2*kk+1][0], sacc[2*kk+1][1]);
            pa[kk][3] = pack2(sacc[2*kk+1][2], sacc[2*kk+1][3]);
        }

        // ---- O += P @ V ----
        #pragma unroll
        for (int kk = 0; kk < 4; kk++) {
            uint32_t bv[16][2];
            #pragma unroll
            for (int nj = 0; nj < 8; nj++) {
                uint32_t bd = smaddr(&Vs[(kk * 16 + (lane & 15)) * VW + nj * 16 + (lane >> 4) * 8]);
                LDSM_X4_T(bv[2*nj][0], bv[2*nj][1], bv[2*nj+1][0], bv[2*nj+1][1], bd);
            }
            #pragma unroll
            for (int ni = 0; ni < 16; ni++)
                MMA16816(oacc[ni][0], oacc[ni][1], oacc[ni][2], oacc[ni][3],
                         pa[kk][0], pa[kk][1], pa[kk][2], pa[kk][3], bv[ni][0], bv[ni][1]);
        }
        __syncthreads();
    }

    float inv0 = 1.f / l0, inv1 = 1.f / l1;
    size_t r0 = (size_t)(b * SS) + qt * 128 + warp * 16 + g;
    #pragma unroll
    for (int ni = 0; ni < 16; ni++) {
        int col = h * DV + ni * 8 + q2;
        *(uint32_t*)&oh[r0 * ODIM + col]       = pack2(oacc[ni][0] * inv0, oacc[ni][1] * inv0);
        *(uint32_t*)&oh[(r0 + 8) * ODIM + col] = pack2(oacc[ni][2] * inv1, oacc[ni][3] * inv1);
    }
}

// ---------------- launch ----------------
extern "C" void kernel_launch(void* const* d_in, const int* in_sizes, int n_in,
                              void* d_out, int out_size)
{
    const float* hs   = (const float*)d_in[0];
    const float* Wqkv = (const float*)d_in[1];
    const float* Wk   = (const float*)d_in[2];
    const float* Wv   = (const float*)d_in[3];
    const float* Wo   = (const float*)d_in[4];
    float* out = (float*)d_out;

    float *ropet;
    __half *hsh, *wqkvT, *wkvT, *qkvh, *kvh, *attnh, *woT;
    cudaGetSymbolAddress((void**)&ropet, g_ropet);
    cudaGetSymbolAddress((void**)&hsh,   g_hsh);
    cudaGetSymbolAddress((void**)&wqkvT, g_wqkvT);
    cudaGetSymbolAddress((void**)&wkvT,  g_wkvT);
    cudaGetSymbolAddress((void**)&qkvh,  g_qkvh);
    cudaGetSymbolAddress((void**)&kvh,   g_kvh);
    cudaGetSymbolAddress((void**)&attnh, g_attnh);
    cudaGetSymbolAddress((void**)&woT,   g_woT);

    cudaFuncSetAttribute((const void*)hgemm<__half, 256>,
                         cudaFuncAttributeMaxDynamicSharedMemorySize, GCfg<256>::SMEM);
    cudaFuncSetAttribute((const void*)hgemm<__half, 128>,
                         cudaFuncAttributeMaxDynamicSharedMemorySize, GCfg<128>::SMEM);
    cudaFuncSetAttribute((const void*)hgemm<float, 256>,
                         cudaFuncAttributeMaxDynamicSharedMemorySize, GCfg<256>::SMEM);
    cudaFuncSetAttribute((const void*)attn_kernel,
                         cudaFuncAttributeMaxDynamicSharedMemorySize, ATTN_SMEM);

    // ---- prep: rope table + input conversion + fused weight transposes ----
    rope_table<<<(SS * 32 + 255) / 256, 256>>>(ropet);
    f2h_slice<<<(NROWS * (HID/4) + 255) / 256, 256>>>(hs, HID, HID, NROWS, hsh);
    transp_all<<<T0 + T1 + T2 + T3, dim3(32, 8)>>>(Wqkv, Wk, Wv, Wo, wqkvT, wkvT, woT);

    // ---- GEMM1: qkvh = hidden @ Wqkv  (fp16 out) ----
    hgemm<__half, 256><<<dim3(QKVN/128, NROWS/256), 256, GCfg<256>::SMEM>>>(
        hsh, HID, wqkvT, HID, qkvh, QKVN, HID);
    // ---- GEMM2 (merged, BM=128 for wave balance): kvh = c_kv @ [Wk|Wv] ----
    hgemm<__half, 128><<<dim3(KVD/128, NROWS/128), 256, GCfg<128>::SMEM>>>(
        qkvh + QDIM, QKVN, wkvT, LORA, kvh, KVD, LORA);
    // ---- RoPE in place on fp16 ----
    rope_apply_h<<<(NROWS * 20 * 32 + 255) / 256, 256>>>(qkvh, kvh, ropet);
    // ---- attention ----
    attn_kernel<<<dim3(SS/128, NH, BB), 256, ATTN_SMEM>>>(
        qkvh, QKVN, kvh, KVD, kvh + KDIM, KVD, attnh);
    // ---- GEMM3: out = attn @ Wo  (fp32 out) ----
    hgemm<float, 256><<<dim3(HID/128, NROWS/256), 256, GCfg<256>::SMEM>>>(
        attnh, ODIM, woT, ODIM, out, HID, ODIM);
}

// round 16
// speedup vs baseline: 1.0393x; 1.0393x over previous
#include <cuda_runtime.h>
#include <cuda_fp16.h>
#include <math.h>
#include <stdint.h>

// ---------------- problem constants ----------------
#define BB    2
#define SS    2048
#define HID   2048
#define NH    16
#define NKV   4
#define DQK   192
#define DV    128
#define LORA  512
#define QKVN  3584                 // NH*DQK + LORA
#define NROWS 4096                 // BB*SS
#define KDIM  768                  // NKV*DQK
#define VDIM  512                  // NKV*DV
#define KVD   1280                 // KDIM + VDIM
#define ODIM  2048                 // NH*DV
#define QDIM  3072                 // NH*DQK

// ---------------- scratch (static device globals) ----------------
__device__ __align__(256) float  g_ropet[SS * 64];
__device__ __align__(256) __half g_hsh  [(size_t)NROWS * HID];
__device__ __align__(256) __half g_wqkvT[(size_t)QKVN * HID];    // [N][K]
__device__ __align__(256) __half g_wkvT [(size_t)KVD * LORA];    // [N][K], k rows then v rows
__device__ __align__(256) __half g_qkvh [(size_t)NROWS * QKVN];  // fp16 GEMM1 out: q | c_kv
__device__ __align__(256) __half g_kvh  [(size_t)NROWS * KVD];   // fp16 GEMM2 out: k | v
__device__ __align__(256) __half g_attnh[(size_t)NROWS * ODIM];
__device__ __align__(256) __half g_woT  [(size_t)HID * ODIM];    // [N=HID][K=ODIM]

// ---------------- helpers ----------------
__device__ __forceinline__ uint32_t smaddr(const void* p) {
    return (uint32_t)__cvta_generic_to_shared(p);
}
__device__ __forceinline__ uint32_t pack2(float x, float y) {
    __half2 h = __floats2half2_rn(x, y);
    return *(uint32_t*)&h;
}
__device__ __forceinline__ void store2(float* p, float a, float b) {
    *(float2*)p = make_float2(a, b);
}
__device__ __forceinline__ void store2(__half* p, float a, float b) {
    *(uint32_t*)p = pack2(a, b);
}
#define CP16(dst, src) \
    asm volatile("cp.async.cg.shared.global [%0], [%1], 16;" :: "r"(dst), "l"(src) : "memory")
#define CP_COMMIT() asm volatile("cp.async.commit_group;" ::: "memory")
#define CP_WAIT(n)  asm volatile("cp.async.wait_group %0;" :: "n"(n) : "memory")

#define LDSM_X4(r0,r1,r2,r3,addr) \
    asm volatile("ldmatrix.sync.aligned.m8n8.x4.shared.b16 {%0,%1,%2,%3}, [%4];" \
                 : "=r"(r0), "=r"(r1), "=r"(r2), "=r"(r3) : "r"(addr))
#define LDSM_X4_T(r0,r1,r2,r3,addr) \
    asm volatile("ldmatrix.sync.aligned.m8n8.x4.trans.shared.b16 {%0,%1,%2,%3}, [%4];" \
                 : "=r"(r0), "=r"(r1), "=r"(r2), "=r"(r3) : "r"(addr))
#define MMA16816(c0,c1,c2,c3,a0,a1,a2,a3,b0,b1) \
    asm volatile("mma.sync.aligned.m16n8k16.row.col.f32.f16.f16.f32 " \
                 "{%0,%1,%2,%3}, {%4,%5,%6,%7}, {%8,%9}, {%0,%1,%2,%3};" \
                 : "+f"(c0), "+f"(c1), "+f"(c2), "+f"(c3) \
                 : "r"(a0), "r"(a1), "r"(a2), "r"(a3), "r"(b0), "r"(b1))

// ---------------- pipelined half GEMM: C[M,N] = A[M,K]h @ Bt[N,K]h ----------------
// BM x 128 x 32 CTA tile, 256 threads, 4-stage cp.async pipeline.
// SINGLE barrier per chunk: refill (stage c+3) issued after compute; the top
// barrier of chunk c proves all warps finished chunk c-1 = last reader of that stage.
template <int BM> struct GCfg {
    static const int NSTG = 4;
    static const int ASTG = BM * 40;
    static const int BSTG = 128 * 40;
    static const int STG  = ASTG + BSTG;
    static const int SMEM = NSTG * STG * 2;     // BM=256: 122880, BM=128: 81920
};

template <typename OutT, int BM>
__global__ void __launch_bounds__(256, 1) hgemm(
    const __half* __restrict__ A, int lda,
    const __half* __restrict__ Bt, int ldb,
    OutT* __restrict__ C, int ldc, int K)
{
    constexpr int NSTG  = GCfg<BM>::NSTG;
    constexpr int ASTG_ = GCfg<BM>::ASTG;
    constexpr int STG   = GCfg<BM>::STG;
    constexpr int NI    = (BM == 256) ? 8 : 4;    // n-frags per warp
    constexpr int ABLK  = BM / 64;

    extern __shared__ __half hsm[];
    const int tid = threadIdx.x, lane = tid & 31, warp = tid >> 5;
    const int wm = (BM == 256) ? (warp >> 1) * 64 : (warp >> 2) * 64;
    const int wn = (BM == 256) ? (warp & 1) * 64  : (warp & 3) * 32;
    const int m0 = blockIdx.y * BM, n0 = blockIdx.x * 128;
    const int g = lane >> 2, q2 = (lane & 3) * 2;
    const int lr = tid >> 2, lc = (tid & 3) * 8;
    const int nchunk = K >> 5;

    float acc[4][NI][4];
    #pragma unroll
    for (int mi = 0; mi < 4; mi++)
        #pragma unroll
        for (int ni = 0; ni < NI; ni++)
            #pragma unroll
            for (int e = 0; e < 4; e++) acc[mi][ni][e] = 0.f;

    // prefetch stages 0..NSTG-2
    #pragma unroll
    for (int p = 0; p < NSTG - 1; p++) {
        __half* As = hsm + p * STG;
        __half* Bs = As + ASTG_;
        int k0 = p * 32;
        #pragma unroll
        for (int bk = 0; bk < ABLK; bk++)
            CP16(smaddr(&As[(lr + 64 * bk) * 40 + lc]),
                 &A[(size_t)(m0 + 64 * bk + lr) * lda + k0 + lc]);
        #pragma unroll
        for (int bk = 0; bk < 2; bk++)
            CP16(smaddr(&Bs[(lr + 64 * bk) * 40 + lc]),
                 &Bt[(size_t)(n0 + 64 * bk + lr) * ldb + k0 + lc]);
        CP_COMMIT();
    }

    for (int c = 0; c < nchunk; c++) {
        CP_WAIT(NSTG - 2);
        __syncthreads();          // the ONLY barrier: stage c resident AND all
                                  // warps finished chunk c-1 (last reader of c+3's stage)
        const int s = c % NSTG;
        __half* As = hsm + s * STG;
        __half* Bs = As + ASTG_;

        #pragma unroll
        for (int kk = 0; kk < 2; kk++) {
            const int ks = kk * 16;
            uint32_t a[4][4], bf[NI][2];
            #pragma unroll
            for (int mi = 0; mi < 4; mi++) {
                uint32_t ad = smaddr(&As[(wm + mi * 16 + (lane & 15)) * 40 + ks + (lane >> 4) * 8]);
                LDSM_X4(a[mi][0], a[mi][1], a[mi][2], a[mi][3], ad);
            }
            #pragma unroll
            for (int nj = 0; nj < NI / 2; nj++) {
                uint32_t bd = smaddr(&Bs[(wn + nj * 16 + (lane & 7) + ((lane >> 4) & 1) * 8) * 40
                                         + ks + ((lane >> 3) & 1) * 8]);
                LDSM_X4(bf[2*nj][0], bf[2*nj][1], bf[2*nj+1][0], bf[2*nj+1][1], bd);
            }
            #pragma unroll
            for (int mi = 0; mi < 4; mi++)
                #pragma unroll
                for (int ni = 0; ni < NI; ni++)
                    MMA16816(acc[mi][ni][0], acc[mi][ni][1], acc[mi][ni][2], acc[mi][ni][3],
                             a[mi][0], a[mi][1], a[mi][2], a[mi][3], bf[ni][0], bf[ni][1]);
        }

        // refill stage c+NSTG-1 (no barrier needed: see comment at top barrier)
        if (c + NSTG - 1 < nchunk) {
            const int s2 = (c + NSTG - 1) % NSTG;
            __half* As2 = hsm + s2 * STG;
            __half* Bs2 = As2 + ASTG_;
            int k0 = (c + NSTG - 1) * 32;
            #pragma unroll
            for (int bk = 0; bk < ABLK; bk++)
                CP16(smaddr(&As2[(lr + 64 * bk) * 40 + lc]),
                     &A[(size_t)(m0 + 64 * bk + lr) * lda + k0 + lc]);
            #pragma unroll
            for (int bk = 0; bk < 2; bk++)
                CP16(smaddr(&Bs2[(lr + 64 * bk) * 40 + lc]),
                     &Bt[(size_t)(n0 + 64 * bk + lr) * ldb + k0 + lc]);
        }
        CP_COMMIT();
    }

    #pragma unroll
    for (int mi = 0; mi < 4; mi++)
        #pragma unroll
        for (int ni = 0; ni < NI; ni++) {
            int row = m0 + wm + mi * 16 + g;
            int col = n0 + wn + ni * 8 + q2;
            store2(C + (size_t)row * ldc + col,       acc[mi][ni][0], acc[mi][ni][1]);
            store2(C + (size_t)(row + 8) * ldc + col, acc[mi][ni][2], acc[mi][ni][3]);
        }
}

// ---------------- conversions ----------------
__global__ void f2h_slice(const float* __restrict__ src, int ld, int cols, int rows,
                          __half* __restrict__ dst)
{
    int i = blockIdx.x * blockDim.x + threadIdx.x;
    int total = rows * (cols >> 2);
    if (i >= total) return;
    int row = i / (cols >> 2);
    int c4  = (i - row * (cols >> 2)) << 2;
    float4 v = *(const float4*)&src[(size_t)row * ld + c4];
    __half2 h0 = __floats2half2_rn(v.x, v.y);
    __half2 h1 = __floats2half2_rn(v.z, v.w);
    uint2 o = make_uint2(*(uint32_t*)&h0, *(uint32_t*)&h1);
    *(uint2*)&dst[(size_t)row * cols + c4] = o;
}

// all four weight transposes fused: flat block id -> segment
#define T0 7168   // Wqkv: (QKVN/32)*(HID/32)
#define T1 384    // Wk:   (KDIM/32)*(LORA/32)
#define T2 256    // Wv:   (VDIM/32)*(LORA/32)
#define T3 4096   // Wo:   (HID/32)*(ODIM/32)
__global__ void transp_all(const float* __restrict__ Wqkv, const float* __restrict__ Wk,
                           const float* __restrict__ Wv,   const float* __restrict__ Wo,
                           __half* __restrict__ wqkvT, __half* __restrict__ wkvT,
                           __half* __restrict__ woT)
{
    __shared__ float t[32][33];
    int id = blockIdx.x;
    const float* W; __half* Wt; int K, N, nx;
    if (id < T0)                  { W = Wqkv; Wt = wqkvT; K = HID;  N = QKVN; nx = QKVN/32; }
    else if ((id -= T0) < T1)     { W = Wk;   Wt = wkvT;  K = LORA; N = KDIM; nx = KDIM/32; }
    else if ((id -= T1) < T2)     { W = Wv;   Wt = wkvT + (size_t)KDIM * LORA; K = LORA; N = VDIM; nx = VDIM/32; }
    else { id -= T2;                W = Wo;   Wt = woT;   K = ODIM; N = HID;  nx = HID/32; }
    int n0 = (id % nx) * 32, k0 = (id / nx) * 32;
    int tx = threadIdx.x, ty = threadIdx.y;   // 32 x 8
    #pragma unroll
    for (int i = 0; i < 4; i++)
        t[ty + i * 8][tx] = W[(size_t)(k0 + ty + i * 8) * N + n0 + tx];
    __syncthreads();
    #pragma unroll
    for (int i = 0; i < 4; i++)
        Wt[(size_t)(n0 + ty + i * 8) * K + k0 + tx] = __float2half(t[tx][ty + i * 8]);
}

// ---------------- RoPE ----------------
__global__ void rope_table(float* __restrict__ tab)
{
    int i = blockIdx.x * blockDim.x + threadIdx.x;
    if (i >= SS * 32) return;
    int t = i >> 5, p = i & 31;
    double f = exp(-((double)(2 * p) / 64.0) * log(10000.0));
    double sd, cd;
    sincos((double)t * f, &sd, &cd);
    tab[t * 64 + p]      = (float)cd;
    tab[t * 64 + 32 + p] = (float)sd;
}

__global__ void rope_apply_h(__half* __restrict__ qkvh, __half* __restrict__ kvh,
                             const float* __restrict__ tab)
{
    int i = blockIdx.x * blockDim.x + threadIdx.x;
    const int total = NROWS * 20 * 32;
    if (i >= total) return;
    int p    = i & 31;
    int rest = i >> 5;
    int slot = rest % 20;
    int row  = rest / 20;
    int t    = row & (SS - 1);
    __half* base = (slot < 16)
        ? (qkvh + (size_t)row * QKVN + slot * DQK + 128)
        : (kvh  + (size_t)row * KVD + (slot - 16) * DQK + 128);
    float c = tab[t * 64 + p], s = tab[t * 64 + 32 + p];
    float x1 = __half2float(base[p]), x2 = __half2float(base[p + 32]);
    base[p]      = __float2half(x1 * c - x2 * s);
    base[p + 32] = __float2half(x2 * c + x1 * s);
}

// ---------------- flash attention (mma, causal, GQA, cp.async double-buffer) ----------------
// R13 structure exactly — untouched this round.
#define QW 200
#define VW 136
#define ATTN_SMEM ((128*QW + 2*64*QW + 2*64*VW) * 2)   // 137216 bytes

__global__ void __launch_bounds__(256, 1) attn_kernel(
    const __half* __restrict__ qp, int ldq,
    const __half* __restrict__ kp2, int ldk,
    const __half* __restrict__ vp2, int ldv,
    __half* __restrict__ oh)
{
    extern __shared__ __half sh[];
    __half* Qs  = sh;                     // [128][QW]
    __half* Ksb = sh + 128 * QW;          // 2 x [64][QW]
    __half* Vsb = Ksb + 2 * 64 * QW;      // 2 x [64][VW]

    const int qt   = gridDim.x - 1 - blockIdx.x;
    const int h    = blockIdx.y, b = blockIdx.z, hkv = h >> 2;
    const int tid  = threadIdx.x, lane = tid & 31, warp = tid >> 5;
    const int g    = lane >> 2, q2 = (lane & 3) * 2;
    const float scale = 0.07216878364870323f;

    for (int f = tid; f < 128 * 24; f += 256) {
        int r = f / 24, c = (f % 24) * 8;
        CP16(smaddr(&Qs[r * QW + c]),
             &qp[(size_t)(b * SS + qt * 128 + r) * ldq + h * DQK + c]);
    }
    {
        const __half* kp = &kp2[(size_t)(b * SS) * ldk + hkv * DQK];
        const __half* vp = &vp2[(size_t)(b * SS) * ldv + hkv * DV];
        for (int f = tid; f < 64 * 24; f += 256) {
            int r = f / 24, c = (f % 24) * 8;
            CP16(smaddr(&Ksb[r * QW + c]), kp + (size_t)r * ldk + c);
        }
        for (int f = tid; f < 64 * 16; f += 256) {
            int r = f / 16, c = (f % 16) * 8;
            CP16(smaddr(&Vsb[r * VW + c]), vp + (size_t)r * ldv + c);
        }
    }
    CP_COMMIT();

    float oacc[16][4];
    #pragma unroll
    for (int ni = 0; ni < 16; ni++)
        #pragma unroll
        for (int e = 0; e < 4; e++) oacc[ni][e] = 0.f;
    float m0 = -1e30f, m1 = -1e30f, l0 = 0.f, l1 = 0.f;

    const int row0 = qt * 128 + warp * 16 + g;
    const int ktend = 2 * qt + 1;

    for (int kt = 0; kt <= ktend; kt++) {
        if (kt < ktend) {
            __half* Kn = Ksb + ((kt + 1) & 1) * 64 * QW;
            __half* Vn = Vsb + ((kt + 1) & 1) * 64 * VW;
            const __half* kp = &kp2[(size_t)(b * SS + (kt + 1) * 64) * ldk + hkv * DQK];
            const __half* vp = &vp2[(size_t)(b * SS + (kt + 1) * 64) * ldv + hkv * DV];
            for (int f = tid; f < 64 * 24; f += 256) {
                int r = f / 24, c = (f % 24) * 8;
                CP16(smaddr(&Kn[r * QW + c]), kp + (size_t)r * ldk + c);
            }
            for (int f = tid; f < 64 * 16; f += 256) {
                int r = f / 16, c = (f % 16) * 8;
                CP16(smaddr(&Vn[r * VW + c]), vp + (size_t)r * ldv + c);
            }
        }
        CP_COMMIT();
        CP_WAIT(1);
        __syncthreads();

        __half* Ks = Ksb + (kt & 1) * 64 * QW;
        __half* Vs = Vsb + (kt & 1) * 64 * VW;

        // ---- S = Q @ K^T ----
        float sacc[8][4];
        #pragma unroll
        for (int j = 0; j < 8; j++)
            #pragma unroll
            for (int e = 0; e < 4; e++) sacc[j][e] = 0.f;

        #pragma unroll
        for (int ks = 0; ks < 12; ks++) {
            uint32_t a0, a1, a2, a3;
            uint32_t ad = smaddr(&Qs[(warp * 16 + (lane & 15)) * QW + ks * 16 + (lane >> 4) * 8]);
            LDSM_X4(a0, a1, a2, a3, ad);
            uint32_t bk[8][2];
            #pragma unroll
            for (int nj = 0; nj < 4; nj++) {
                uint32_t bd = smaddr(&Ks[(nj * 16 + (lane & 7) + ((lane >> 4) & 1) * 8) * QW
                                         + ks * 16 + ((lane >> 3) & 1) * 8]);
                LDSM_X4(bk[2*nj][0], bk[2*nj][1], bk[2*nj+1][0], bk[2*nj+1][1], bd);
            }
            #pragma unroll
            for (int nj = 0; nj < 8; nj++)
                MMA16816(sacc[nj][0], sacc[nj][1], sacc[nj][2], sacc[nj][3],
                         a0, a1, a2, a3, bk[nj][0], bk[nj][1]);
        }

        // ---- scale + mask + online softmax ----
        const bool diag = (kt >= 2 * qt);
        float mx0 = -1e30f, mx1 = -1e30f;
        #pragma unroll
        for (int j = 0; j < 8; j++) {
            #pragma unroll
            for (int e = 0; e < 4; e++) {
                float v = sacc[j][e] * scale;
                if (diag) {
                    int col = kt * 64 + j * 8 + q2 + (e & 1);
                    int row = row0 + ((e >= 2) ? 8 : 0);
                    if (col > row) v = -1e30f;
                }
                sacc[j][e] = v;
            }
            mx0 = fmaxf(mx0, fmaxf(sacc[j][0], sacc[j][1]));
            mx1 = fmaxf(mx1, fmaxf(sacc[j][2], sacc[j][3]));
        }
        mx0 = fmaxf(mx0, __shfl_xor_sync(0xffffffffu, mx0, 1));
        mx0 = fmaxf(mx0, __shfl_xor_sync(0xffffffffu, mx0, 2));
        mx1 = fmaxf(mx1, __shfl_xor_sync(0xffffffffu, mx1, 1));
        mx1 = fmaxf(mx1, __shfl_xor_sync(0xffffffffu, mx1, 2));
        float nm0 = fmaxf(m0, mx0), nm1 = fmaxf(m1, mx1);
        float s0 = 0.f, s1 = 0.f;
        #pragma unroll
        for (int j = 0; j < 8; j++) {
            float p0 = __expf(sacc[j][0] - nm0);
            float p1 = __expf(sacc[j][1] - nm0);
            float p2 = __expf(sacc[j][2] - nm1);
            float p3 = __expf(sacc[j][3] - nm1);
            sacc[j][0] = p0; sacc[j][1] = p1; sacc[j][2] = p2; sacc[j][3] = p3;
            s0 += p0 + p1; s1 += p2 + p3;
        }
        s0 += __shfl_xor_sync(0xffffffffu, s0, 1);
        s0 += __shfl_xor_sync(0xffffffffu, s0, 2);
        s1 += __shfl_xor_sync(0xffffffffu, s1, 1);
        s1 += __shfl_xor_sync(0xffffffffu, s1, 2);
        float c0 = __expf(m0 - nm0), c1 = __expf(m1 - nm1);
        l0 = l0 * c0 + s0; l1 = l1 * c1 + s1;
        m0 = nm0; m1 = nm1;
        #pragma unroll
        for (int ni = 0; ni < 16; ni++) {
            oacc[ni][0] *= c0; oacc[ni][1] *= c0;
            oacc[ni][2] *= c1; oacc[ni][3] *= c1;
        }

        uint32_t pa[4][4];
        #pragma unroll
        for (int kk = 0; kk < 4; kk++) {
            pa[kk][0] = pack2(sacc[2*kk][0],   sacc[2*kk][1]);
            pa[kk][1] = pack2(sacc[2*kk][2],   sacc[2*kk][3]);
            pa[kk][2] = pack2(sacc[2*kk+1][0], sacc[2*kk+1][1]);
            pa[kk][3] = pack2(sacc[2*kk+1][2], sacc[2*kk+1][3]);
        }

        // ---- O += P @ V ----
        #pragma unroll
        for (int kk = 0; kk < 4; kk++) {
            uint32_t bv[16][2];
            #pragma unroll
            for (int nj = 0; nj < 8; nj++) {
                uint32_t bd = smaddr(&Vs[(kk * 16 + (lane & 15)) * VW + nj * 16 + (lane >> 4) * 8]);
                LDSM_X4_T(bv[2*nj][0], bv[2*nj][1], bv[2*nj+1][0], bv[2*nj+1][1], bd);
            }
            #pragma unroll
            for (int ni = 0; ni < 16; ni++)
                MMA16816(oacc[ni][0], oacc[ni][1], oacc[ni][2], oacc[ni][3],
                         pa[kk][0], pa[kk][1], pa[kk][2], pa[kk][3], bv[ni][0], bv[ni][1]);
        }
        __syncthreads();
    }

    float inv0 = 1.f / l0, inv1 = 1.f / l1;
    size_t r0 = (size_t)(b * SS) + qt * 128 + warp * 16 + g;
    #pragma unroll
    for (int ni = 0; ni < 16; ni++) {
        int col = h * DV + ni * 8 + q2;
        *(uint32_t*)&oh[r0 * ODIM + col]       = pack2(oacc[ni][0] * inv0, oacc[ni][1] * inv0);
        *(uint32_t*)&oh[(r0 + 8) * ODIM + col] = pack2(oacc[ni][2] * inv1, oacc[ni][3] * inv1);
    }
}

// ---------------- launch ----------------
extern "C" void kernel_launch(void* const* d_in, const int* in_sizes, int n_in,
                              void* d_out, int out_size)
{
    const float* hs   = (const float*)d_in[0];
    const float* Wqkv = (const float*)d_in[1];
    const float* Wk   = (const float*)d_in[2];
    const float* Wv   = (const float*)d_in[3];
    const float* Wo   = (const float*)d_in[4];
    float* out = (float*)d_out;

    float *ropet;
    __half *hsh, *wqkvT, *wkvT, *qkvh, *kvh, *attnh, *woT;
    cudaGetSymbolAddress((void**)&ropet, g_ropet);
    cudaGetSymbolAddress((void**)&hsh,   g_hsh);
    cudaGetSymbolAddress((void**)&wqkvT, g_wqkvT);
    cudaGetSymbolAddress((void**)&wkvT,  g_wkvT);
    cudaGetSymbolAddress((void**)&qkvh,  g_qkvh);
    cudaGetSymbolAddress((void**)&kvh,   g_kvh);
    cudaGetSymbolAddress((void**)&attnh, g_attnh);
    cudaGetSymbolAddress((void**)&woT,   g_woT);

    cudaFuncSetAttribute((const void*)hgemm<__half, 256>,
                         cudaFuncAttributeMaxDynamicSharedMemorySize, GCfg<256>::SMEM);
    cudaFuncSetAttribute((const void*)hgemm<__half, 128>,
                         cudaFuncAttributeMaxDynamicSharedMemorySize, GCfg<128>::SMEM);
    cudaFuncSetAttribute((const void*)hgemm<float, 256>,
                         cudaFuncAttributeMaxDynamicSharedMemorySize, GCfg<256>::SMEM);
    cudaFuncSetAttribute((const void*)attn_kernel,
                         cudaFuncAttributeMaxDynamicSharedMemorySize, ATTN_SMEM);

    // ---- prep: rope table + input conversion + fused weight transposes ----
    rope_table<<<(SS * 32 + 255) / 256, 256>>>(ropet);
    f2h_slice<<<(NROWS * (HID/4) + 255) / 256, 256>>>(hs, HID, HID, NROWS, hsh);
    transp_all<<<T0 + T1 + T2 + T3, dim3(32, 8)>>>(Wqkv, Wk, Wv, Wo, wqkvT, wkvT, woT);

    // ---- GEMM1: qkvh = hidden @ Wqkv  (fp16 out) ----
    hgemm<__half, 256><<<dim3(QKVN/128, NROWS/256), 256, GCfg<256>::SMEM>>>(
        hsh, HID, wqkvT, HID, qkvh, QKVN, HID);
    // ---- GEMM2 (merged, BM=128 for wave balance): kvh = c_kv @ [Wk|Wv] ----
    hgemm<__half, 128><<<dim3(KVD/128, NROWS/128), 256, GCfg<128>::SMEM>>>(
        qkvh + QDIM, QKVN, wkvT, LORA, kvh, KVD, LORA);
    // ---- RoPE in place on fp16 ----
    rope_apply_h<<<(NROWS * 20 * 32 + 255) / 256, 256>>>(qkvh, kvh, ropet);
    // ---- attention ----
    attn_kernel<<<dim3(SS/128, NH, BB), 256, ATTN_SMEM>>>(
        qkvh, QKVN, kvh, KVD, kvh + KDIM, KVD, attnh);
    // ---- GEMM3: out = attn @ Wo  (fp32 out) ----
    hgemm<float, 256><<<dim3(HID/128, NROWS/256), 256, GCfg<256>::SMEM>>>(
        attnh, ODIM, woT, ODIM, out, HID, ODIM);
}

// round 17
// speedup vs baseline: 1.0863x; 1.0452x over previous
#include <cuda_runtime.h>
#include <cuda_fp16.h>
#include <math.h>
#include <stdint.h>

// ---------------- problem constants ----------------
#define BB    2
#define SS    2048
#define HID   2048
#define NH    16
#define NKV   4
#define DQK   192
#define DV    128
#define LORA  512
#define QKVN  3584                 // NH*DQK + LORA
#define NROWS 4096                 // BB*SS
#define KDIM  768                  // NKV*DQK
#define VDIM  512                  // NKV*DV
#define KVD   1280                 // KDIM + VDIM
#define ODIM  2048                 // NH*DV
#define QDIM  3072                 // NH*DQK

// ---------------- scratch (static device globals) ----------------
__device__ __align__(256) float  g_ropet[SS * 64];
__device__ __align__(256) __half g_hsh  [(size_t)NROWS * HID];
__device__ __align__(256) __half g_wqkvT[(size_t)QKVN * HID];    // [N][K]
__device__ __align__(256) __half g_wkvT [(size_t)KVD * LORA];    // [N][K], k rows then v rows
__device__ __align__(256) __half g_qkvh [(size_t)NROWS * QKVN];  // fp16 GEMM1 out: q | c_kv
__device__ __align__(256) __half g_kvh  [(size_t)NROWS * KVD];   // fp16 GEMM2 out: k | v
__device__ __align__(256) __half g_attnh[(size_t)NROWS * ODIM];
__device__ __align__(256) __half g_woT  [(size_t)HID * ODIM];    // [N=HID][K=ODIM]

// ---------------- helpers ----------------
__device__ __forceinline__ uint32_t smaddr(const void* p) {
    return (uint32_t)__cvta_generic_to_shared(p);
}
__device__ __forceinline__ uint32_t pack2(float x, float y) {
    __half2 h = __floats2half2_rn(x, y);
    return *(uint32_t*)&h;
}
__device__ __forceinline__ void store2(float* p, float a, float b) {
    *(float2*)p = make_float2(a, b);
}
__device__ __forceinline__ void store2(__half* p, float a, float b) {
    *(uint32_t*)p = pack2(a, b);
}
#define CP16(dst, src) \
    asm volatile("cp.async.cg.shared.global [%0], [%1], 16;" :: "r"(dst), "l"(src) : "memory")
#define CP_COMMIT() asm volatile("cp.async.commit_group;" ::: "memory")
#define CP_WAIT(n)  asm volatile("cp.async.wait_group %0;" :: "n"(n) : "memory")

#define LDSM_X4(r0,r1,r2,r3,addr) \
    asm volatile("ldmatrix.sync.aligned.m8n8.x4.shared.b16 {%0,%1,%2,%3}, [%4];" \
                 : "=r"(r0), "=r"(r1), "=r"(r2), "=r"(r3) : "r"(addr))
#define LDSM_X4_T(r0,r1,r2,r3,addr) \
    asm volatile("ldmatrix.sync.aligned.m8n8.x4.trans.shared.b16 {%0,%1,%2,%3}, [%4];" \
                 : "=r"(r0), "=r"(r1), "=r"(r2), "=r"(r3) : "r"(addr))
#define MMA16816(c0,c1,c2,c3,a0,a1,a2,a3,b0,b1) \
    asm volatile("mma.sync.aligned.m16n8k16.row.col.f32.f16.f16.f32 " \
                 "{%0,%1,%2,%3}, {%4,%5,%6,%7}, {%8,%9}, {%0,%1,%2,%3};" \
                 : "+f"(c0), "+f"(c1), "+f"(c2), "+f"(c3) \
                 : "r"(a0), "r"(a1), "r"(a2), "r"(a3), "r"(b0), "r"(b1))

// ---------------- pipelined half GEMM: C[M,N] = A[M,K]h @ Bt[N,K]h ----------------
// R15 structure exactly (best known): BMx128x32, 4 stages, single barrier/chunk.
template <int BM> struct GCfg {
    static const int NSTG = 4;
    static const int ASTG = BM * 40;
    static const int BSTG = 128 * 40;
    static const int STG  = ASTG + BSTG;
    static const int SMEM = NSTG * STG * 2;     // BM=256: 122880, BM=128: 81920
};

template <typename OutT, int BM>
__global__ void __launch_bounds__(256, 1) hgemm(
    const __half* __restrict__ A, int lda,
    const __half* __restrict__ Bt, int ldb,
    OutT* __restrict__ C, int ldc, int K)
{
    constexpr int NSTG  = GCfg<BM>::NSTG;
    constexpr int ASTG_ = GCfg<BM>::ASTG;
    constexpr int STG   = GCfg<BM>::STG;
    constexpr int NI    = (BM == 256) ? 8 : 4;
    constexpr int ABLK  = BM / 64;

    extern __shared__ __half hsm[];
    const int tid = threadIdx.x, lane = tid & 31, warp = tid >> 5;
    const int wm = (BM == 256) ? (warp >> 1) * 64 : (warp >> 2) * 64;
    const int wn = (BM == 256) ? (warp & 1) * 64  : (warp & 3) * 32;
    const int m0 = blockIdx.y * BM, n0 = blockIdx.x * 128;
    const int g = lane >> 2, q2 = (lane & 3) * 2;
    const int lr = tid >> 2, lc = (tid & 3) * 8;
    const int nchunk = K >> 5;

    float acc[4][NI][4];
    #pragma unroll
    for (int mi = 0; mi < 4; mi++)
        #pragma unroll
        for (int ni = 0; ni < NI; ni++)
            #pragma unroll
            for (int e = 0; e < 4; e++) acc[mi][ni][e] = 0.f;

    #pragma unroll
    for (int p = 0; p < NSTG - 1; p++) {
        __half* As = hsm + p * STG;
        __half* Bs = As + ASTG_;
        int k0 = p * 32;
        #pragma unroll
        for (int bk = 0; bk < ABLK; bk++)
            CP16(smaddr(&As[(lr + 64 * bk) * 40 + lc]),
                 &A[(size_t)(m0 + 64 * bk + lr) * lda + k0 + lc]);
        #pragma unroll
        for (int bk = 0; bk < 2; bk++)
            CP16(smaddr(&Bs[(lr + 64 * bk) * 40 + lc]),
                 &Bt[(size_t)(n0 + 64 * bk + lr) * ldb + k0 + lc]);
        CP_COMMIT();
    }

    for (int c = 0; c < nchunk; c++) {
        CP_WAIT(NSTG - 2);
        __syncthreads();          // only barrier per chunk (see R15 proof)
        const int s = c % NSTG;
        __half* As = hsm + s * STG;
        __half* Bs = As + ASTG_;

        #pragma unroll
        for (int kk = 0; kk < 2; kk++) {
            const int ks = kk * 16;
            uint32_t a[4][4], bf[NI][2];
            #pragma unroll
            for (int mi = 0; mi < 4; mi++) {
                uint32_t ad = smaddr(&As[(wm + mi * 16 + (lane & 15)) * 40 + ks + (lane >> 4) * 8]);
                LDSM_X4(a[mi][0], a[mi][1], a[mi][2], a[mi][3], ad);
            }
            #pragma unroll
            for (int nj = 0; nj < NI / 2; nj++) {
                uint32_t bd = smaddr(&Bs[(wn + nj * 16 + (lane & 7) + ((lane >> 4) & 1) * 8) * 40
                                         + ks + ((lane >> 3) & 1) * 8]);
                LDSM_X4(bf[2*nj][0], bf[2*nj][1], bf[2*nj+1][0], bf[2*nj+1][1], bd);
            }
            #pragma unroll
            for (int mi = 0; mi < 4; mi++)
                #pragma unroll
                for (int ni = 0; ni < NI; ni++)
                    MMA16816(acc[mi][ni][0], acc[mi][ni][1], acc[mi][ni][2], acc[mi][ni][3],
                             a[mi][0], a[mi][1], a[mi][2], a[mi][3], bf[ni][0], bf[ni][1]);
        }

        if (c + NSTG - 1 < nchunk) {
            const int s2 = (c + NSTG - 1) % NSTG;
            __half* As2 = hsm + s2 * STG;
            __half* Bs2 = As2 + ASTG_;
            int k0 = (c + NSTG - 1) * 32;
            #pragma unroll
            for (int bk = 0; bk < ABLK; bk++)
                CP16(smaddr(&As2[(lr + 64 * bk) * 40 + lc]),
                     &A[(size_t)(m0 + 64 * bk + lr) * lda + k0 + lc]);
            #pragma unroll
            for (int bk = 0; bk < 2; bk++)
                CP16(smaddr(&Bs2[(lr + 64 * bk) * 40 + lc]),
                     &Bt[(size_t)(n0 + 64 * bk + lr) * ldb + k0 + lc]);
        }
        CP_COMMIT();
    }

    #pragma unroll
    for (int mi = 0; mi < 4; mi++)
        #pragma unroll
        for (int ni = 0; ni < NI; ni++) {
            int row = m0 + wm + mi * 16 + g;
            int col = n0 + wn + ni * 8 + q2;
            store2(C + (size_t)row * ldc + col,       acc[mi][ni][0], acc[mi][ni][1]);
            store2(C + (size_t)(row + 8) * ldc + col, acc[mi][ni][2], acc[mi][ni][3]);
        }
}

// ---------------- conversions ----------------
__global__ void f2h_slice(const float* __restrict__ src, int ld, int cols, int rows,
                          __half* __restrict__ dst)
{
    int i = blockIdx.x * blockDim.x + threadIdx.x;
    int total = rows * (cols >> 2);
    if (i >= total) return;
    int row = i / (cols >> 2);
    int c4  = (i - row * (cols >> 2)) << 2;
    float4 v = *(const float4*)&src[(size_t)row * ld + c4];
    __half2 h0 = __floats2half2_rn(v.x, v.y);
    __half2 h1 = __floats2half2_rn(v.z, v.w);
    uint2 o = make_uint2(*(uint32_t*)&h0, *(uint32_t*)&h1);
    *(uint2*)&dst[(size_t)row * cols + c4] = o;
}

// all four weight transposes fused: flat block id -> segment
#define T0 7168   // Wqkv
#define T1 384    // Wk
#define T2 256    // Wv
#define T3 4096   // Wo
__global__ void transp_all(const float* __restrict__ Wqkv, const float* __restrict__ Wk,
                           const float* __restrict__ Wv,   const float* __restrict__ Wo,
                           __half* __restrict__ wqkvT, __half* __restrict__ wkvT,
                           __half* __restrict__ woT)
{
    __shared__ float t[32][33];
    int id = blockIdx.x;
    const float* W; __half* Wt; int K, N, nx;
    if (id < T0)                  { W = Wqkv; Wt = wqkvT; K = HID;  N = QKVN; nx = QKVN/32; }
    else if ((id -= T0) < T1)     { W = Wk;   Wt = wkvT;  K = LORA; N = KDIM; nx = KDIM/32; }
    else if ((id -= T1) < T2)     { W = Wv;   Wt = wkvT + (size_t)KDIM * LORA; K = LORA; N = VDIM; nx = VDIM/32; }
    else { id -= T2;                W = Wo;   Wt = woT;   K = ODIM; N = HID;  nx = HID/32; }
    int n0 = (id % nx) * 32, k0 = (id / nx) * 32;
    int tx = threadIdx.x, ty = threadIdx.y;   // 32 x 8
    #pragma unroll
    for (int i = 0; i < 4; i++)
        t[ty + i * 8][tx] = W[(size_t)(k0 + ty + i * 8) * N + n0 + tx];
    __syncthreads();
    #pragma unroll
    for (int i = 0; i < 4; i++)
        Wt[(size_t)(n0 + ty + i * 8) * K + k0 + tx] = __float2half(t[tx][ty + i * 8]);
}

// ---------------- RoPE ----------------
__global__ void rope_table(float* __restrict__ tab)
{
    int i = blockIdx.x * blockDim.x + threadIdx.x;
    if (i >= SS * 32) return;
    int t = i >> 5, p = i & 31;
    double f = exp(-((double)(2 * p) / 64.0) * log(10000.0));
    double sd, cd;
    sincos((double)t * f, &sd, &cd);
    tab[t * 64 + p]      = (float)cd;
    tab[t * 64 + 32 + p] = (float)sd;
}

__global__ void rope_apply_h(__half* __restrict__ qkvh, __half* __restrict__ kvh,
                             const float* __restrict__ tab)
{
    int i = blockIdx.x * blockDim.x + threadIdx.x;
    const int total = NROWS * 20 * 32;
    if (i >= total) return;
    int p    = i & 31;
    int rest = i >> 5;
    int slot = rest % 20;
    int row  = rest / 20;
    int t    = row & (SS - 1);
    __half* base = (slot < 16)
        ? (qkvh + (size_t)row * QKVN + slot * DQK + 128)
        : (kvh  + (size_t)row * KVD + (slot - 16) * DQK + 128);
    float c = tab[t * 64 + p], s = tab[t * 64 + 32 + p];
    float x1 = __half2float(base[p]), x2 = __half2float(base[p + 32]);
    base[p]      = __float2half(x1 * c - x2 * s);
    base[p + 32] = __float2half(x2 * c + x1 * s);
}

// ---------------- flash attention (mma, causal, GQA) ----------------
// Br=64, 128 threads (4 warps), 2 CTAs/SM. Per-warp fragment code identical to
// the proven R13 shape (warp = 16 rows x 64 cols). KV double-buffered cp.async.
#define QW 200
#define VW 136
#define ATTN_SMEM ((64*QW + 2*64*QW + 2*64*VW) * 2)   // 111616 bytes -> 2 CTAs/SM

__global__ void __launch_bounds__(128, 2) attn_kernel(
    const __half* __restrict__ qp, int ldq,
    const __half* __restrict__ kp2, int ldk,
    const __half* __restrict__ vp2, int ldv,
    __half* __restrict__ oh)
{
    extern __shared__ __half sh[];
    __half* Qs  = sh;                     // [64][QW]
    __half* Ksb = sh + 64 * QW;           // 2 x [64][QW]
    __half* Vsb = Ksb + 2 * 64 * QW;      // 2 x [64][VW]

    const int qt   = gridDim.x - 1 - blockIdx.x;   // heavy tiles first
    const int h    = blockIdx.y, b = blockIdx.z, hkv = h >> 2;
    const int tid  = threadIdx.x, lane = tid & 31, warp = tid >> 5;   // warp 0..3
    const int g    = lane >> 2, q2 = (lane & 3) * 2;
    const float scale = 0.07216878364870323f;

    // prologue: Q tile (64 x 192) + kv tile 0, one cp.async group
    for (int f = tid; f < 64 * 24; f += 128) {
        int r = f / 24, c = (f % 24) * 8;
        CP16(smaddr(&Qs[r * QW + c]),
             &qp[(size_t)(b * SS + qt * 64 + r) * ldq + h * DQK + c]);
    }
    {
        const __half* kp = &kp2[(size_t)(b * SS) * ldk + hkv * DQK];
        const __half* vp = &vp2[(size_t)(b * SS) * ldv + hkv * DV];
        for (int f = tid; f < 64 * 24; f += 128) {
            int r = f / 24, c = (f % 24) * 8;
            CP16(smaddr(&Ksb[r * QW + c]), kp + (size_t)r * ldk + c);
        }
        for (int f = tid; f < 64 * 16; f += 128) {
            int r = f / 16, c = (f % 16) * 8;
            CP16(smaddr(&Vsb[r * VW + c]), vp + (size_t)r * ldv + c);
        }
    }
    CP_COMMIT();

    float oacc[16][4];
    #pragma unroll
    for (int ni = 0; ni < 16; ni++)
        #pragma unroll
        for (int e = 0; e < 4; e++) oacc[ni][e] = 0.f;
    float m0 = -1e30f, m1 = -1e30f, l0 = 0.f, l1 = 0.f;

    const int row0 = qt * 64 + warp * 16 + g;
    const int ktend = qt;                 // kv tiles 0..qt (64-granularity)

    for (int kt = 0; kt <= ktend; kt++) {
        if (kt < ktend) {
            __half* Kn = Ksb + ((kt + 1) & 1) * 64 * QW;
            __half* Vn = Vsb + ((kt + 1) & 1) * 64 * VW;
            const __half* kp = &kp2[(size_t)(b * SS + (kt + 1) * 64) * ldk + hkv * DQK];
            const __half* vp = &vp2[(size_t)(b * SS + (kt + 1) * 64) * ldv + hkv * DV];
            for (int f = tid; f < 64 * 24; f += 128) {
                int r = f / 24, c = (f % 24) * 8;
                CP16(smaddr(&Kn[r * QW + c]), kp + (size_t)r * ldk + c);
            }
            for (int f = tid; f < 64 * 16; f += 128) {
                int r = f / 16, c = (f % 16) * 8;
                CP16(smaddr(&Vn[r * VW + c]), vp + (size_t)r * ldv + c);
            }
        }
        CP_COMMIT();
        CP_WAIT(1);
        __syncthreads();

        __half* Ks = Ksb + (kt & 1) * 64 * QW;
        __half* Vs = Vsb + (kt & 1) * 64 * VW;

        // ---- S = Q @ K^T  (warp: 16 x 64) ----
        float sacc[8][4];
        #pragma unroll
        for (int j = 0; j < 8; j++)
            #pragma unroll
            for (int e = 0; e < 4; e++) sacc[j][e] = 0.f;

        #pragma unroll
        for (int ks = 0; ks < 12; ks++) {
            uint32_t a0, a1, a2, a3;
            uint32_t ad = smaddr(&Qs[(warp * 16 + (lane & 15)) * QW + ks * 16 + (lane >> 4) * 8]);
            LDSM_X4(a0, a1, a2, a3, ad);
            uint32_t bk[8][2];
            #pragma unroll
            for (int nj = 0; nj < 4; nj++) {
                uint32_t bd = smaddr(&Ks[(nj * 16 + (lane & 7) + ((lane >> 4) & 1) * 8) * QW
                                         + ks * 16 + ((lane >> 3) & 1) * 8]);
                LDSM_X4(bk[2*nj][0], bk[2*nj][1], bk[2*nj+1][0], bk[2*nj+1][1], bd);
            }
            #pragma unroll
            for (int nj = 0; nj < 8; nj++)
                MMA16816(sacc[nj][0], sacc[nj][1], sacc[nj][2], sacc[nj][3],
                         a0, a1, a2, a3, bk[nj][0], bk[nj][1]);
        }

        // ---- scale + mask + online softmax ----
        const bool diag = (kt == qt);
        float mx0 = -1e30f, mx1 = -1e30f;
        #pragma unroll
        for (int j = 0; j < 8; j++) {
            #pragma unroll
            for (int e = 0; e < 4; e++) {
                float v = sacc[j][e] * scale;
                if (diag) {
                    int col = kt * 64 + j * 8 + q2 + (e & 1);
                    int row = row0 + ((e >= 2) ? 8 : 0);
                    if (col > row) v = -1e30f;
                }
                sacc[j][e] = v;
            }
            mx0 = fmaxf(mx0, fmaxf(sacc[j][0], sacc[j][1]));
            mx1 = fmaxf(mx1, fmaxf(sacc[j][2], sacc[j][3]));
        }
        mx0 = fmaxf(mx0, __shfl_xor_sync(0xffffffffu, mx0, 1));
        mx0 = fmaxf(mx0, __shfl_xor_sync(0xffffffffu, mx0, 2));
        mx1 = fmaxf(mx1, __shfl_xor_sync(0xffffffffu, mx1, 1));
        mx1 = fmaxf(mx1, __shfl_xor_sync(0xffffffffu, mx1, 2));
        float nm0 = fmaxf(m0, mx0), nm1 = fmaxf(m1, mx1);
        float s0 = 0.f, s1 = 0.f;
        #pragma unroll
        for (int j = 0; j < 8; j++) {
            float p0 = __expf(sacc[j][0] - nm0);
            float p1 = __expf(sacc[j][1] - nm0);
            float p2 = __expf(sacc[j][2] - nm1);
            float p3 = __expf(sacc[j][3] - nm1);
            sacc[j][0] = p0; sacc[j][1] = p1; sacc[j][2] = p2; sacc[j][3] = p3;
            s0 += p0 + p1; s1 += p2 + p3;
        }
        s0 += __shfl_xor_sync(0xffffffffu, s0, 1);
        s0 += __shfl_xor_sync(0xffffffffu, s0, 2);
        s1 += __shfl_xor_sync(0xffffffffu, s1, 1);
        s1 += __shfl_xor_sync(0xffffffffu, s1, 2);
        float c0 = __expf(m0 - nm0), c1 = __expf(m1 - nm1);
        l0 = l0 * c0 + s0; l1 = l1 * c1 + s1;
        m0 = nm0; m1 = nm1;
        #pragma unroll
        for (int ni = 0; ni < 16; ni++) {
            oacc[ni][0] *= c0; oacc[ni][1] *= c0;
            oacc[ni][2] *= c1; oacc[ni][3] *= c1;
        }

        uint32_t pa[4][4];
        #pragma unroll
        for (int kk = 0; kk < 4; kk++) {
            pa[kk][0] = pack2(sacc[2*kk][0],   sacc[2*kk][1]);
            pa[kk][1] = pack2(sacc[2*kk][2],   sacc[2*kk][3]);
            pa[kk][2] = pack2(sacc[2*kk+1][0], sacc[2*kk+1][1]);
            pa[kk][3] = pack2(sacc[2*kk+1][2], sacc[2*kk+1][3]);
        }

        // ---- O += P @ V  (warp: 16 x 128) ----
        #pragma unroll
        for (int kk = 0; kk < 4; kk++) {
            uint32_t bv[16][2];
            #pragma unroll
            for (int nj = 0; nj < 8; nj++) {
                uint32_t bd = smaddr(&Vs[(kk * 16 + (lane & 15)) * VW + nj * 16 + (lane >> 4) * 8]);
                LDSM_X4_T(bv[2*nj][0], bv[2*nj][1], bv[2*nj+1][0], bv[2*nj+1][1], bd);
            }
            #pragma unroll
            for (int ni = 0; ni < 16; ni++)
                MMA16816(oacc[ni][0], oacc[ni][1], oacc[ni][2], oacc[ni][3],
                         pa[kk][0], pa[kk][1], pa[kk][2], pa[kk][3], bv[ni][0], bv[ni][1]);
        }
        __syncthreads();
    }

    float inv0 = 1.f / l0, inv1 = 1.f / l1;
    size_t r0 = (size_t)(b * SS) + qt * 64 + warp * 16 + g;
    #pragma unroll
    for (int ni = 0; ni < 16; ni++) {
        int col = h * DV + ni * 8 + q2;
        *(uint32_t*)&oh[r0 * ODIM + col]       = pack2(oacc[ni][0] * inv0, oacc[ni][1] * inv0);
        *(uint32_t*)&oh[(r0 + 8) * ODIM + col] = pack2(oacc[ni][2] * inv1, oacc[ni][3] * inv1);
    }
}

// ---------------- launch ----------------
extern "C" void kernel_launch(void* const* d_in, const int* in_sizes, int n_in,
                              void* d_out, int out_size)
{
    const float* hs   = (const float*)d_in[0];
    const float* Wqkv = (const float*)d_in[1];
    const float* Wk   = (const float*)d_in[2];
    const float* Wv   = (const float*)d_in[3];
    const float* Wo   = (const float*)d_in[4];
    float* out = (float*)d_out;

    float *ropet;
    __half *hsh, *wqkvT, *wkvT, *qkvh, *kvh, *attnh, *woT;
    cudaGetSymbolAddress((void**)&ropet, g_ropet);
    cudaGetSymbolAddress((void**)&hsh,   g_hsh);
    cudaGetSymbolAddress((void**)&wqkvT, g_wqkvT);
    cudaGetSymbolAddress((void**)&wkvT,  g_wkvT);
    cudaGetSymbolAddress((void**)&qkvh,  g_qkvh);
    cudaGetSymbolAddress((void**)&kvh,   g_kvh);
    cudaGetSymbolAddress((void**)&attnh, g_attnh);
    cudaGetSymbolAddress((void**)&woT,   g_woT);

    cudaFuncSetAttribute((const void*)hgemm<__half, 256>,
                         cudaFuncAttributeMaxDynamicSharedMemorySize, GCfg<256>::SMEM);
    cudaFuncSetAttribute((const void*)hgemm<__half, 128>,
                         cudaFuncAttributeMaxDynamicSharedMemorySize, GCfg<128>::SMEM);
    cudaFuncSetAttribute((const void*)hgemm<float, 256>,
                         cudaFuncAttributeMaxDynamicSharedMemorySize, GCfg<256>::SMEM);
    cudaFuncSetAttribute((const void*)attn_kernel,
                         cudaFuncAttributeMaxDynamicSharedMemorySize, ATTN_SMEM);

    // ---- prep ----
    rope_table<<<(SS * 32 + 255) / 256, 256>>>(ropet);
    f2h_slice<<<(NROWS * (HID/4) + 255) / 256, 256>>>(hs, HID, HID, NROWS, hsh);
    transp_all<<<T0 + T1 + T2 + T3, dim3(32, 8)>>>(Wqkv, Wk, Wv, Wo, wqkvT, wkvT, woT);

    // ---- GEMM1 ----
    hgemm<__half, 256><<<dim3(QKVN/128, NROWS/256), 256, GCfg<256>::SMEM>>>(
        hsh, HID, wqkvT, HID, qkvh, QKVN, HID);
    // ---- GEMM2 ----
    hgemm<__half, 128><<<dim3(KVD/128, NROWS/128), 256, GCfg<128>::SMEM>>>(
        qkvh + QDIM, QKVN, wkvT, LORA, kvh, KVD, LORA);
    // ---- RoPE ----
    rope_apply_h<<<(NROWS * 20 * 32 + 255) / 256, 256>>>(qkvh, kvh, ropet);
    // ---- attention: Br=64, 128 threads, 2 CTAs/SM ----
    attn_kernel<<<dim3(SS/64, NH, BB), 128, ATTN_SMEM>>>(
        qkvh, QKVN, kvh, KVD, kvh + KDIM, KVD, attnh);
    // ---- GEMM3 ----
    hgemm<float, 256><<<dim3(HID/128, NROWS/256), 256, GCfg<256>::SMEM>>>(
        attnh, ODIM, woT, ODIM, out, HID, ODIM);
}